// round 12
// baseline (speedup 1.0000x reference)
#include <cuda_runtime.h>
#include <cstdint>
#include <math.h>

#define NODE_DIM_   128
#define NUM_IRREPS_ 224
#define SPH_DIM_    480
#define HIDDEN_     576
#define NUM_BASIS_  20
#define N_NODES_    30000
#define N_EDGES_    480000
#define EPB_        8
#define MAXD_       16
#define SORT_BLKS_  148
// dynamic smem: gates [16][448] + rsh stage [16][480]
#define GATE_FLOATS_ (MAXD_ * 2 * NUM_IRREPS_)
#define DYN_BYTES_   ((GATE_FLOATS_ + MAXD_ * SPH_DIM_) * 4)   // 59392

// Scratch (device globals)
__device__ float g_hidden[(size_t)N_NODES_ * NODE_DIM_];
__device__ float g_scalar_out[(size_t)N_NODES_ * HIDDEN_];
__device__ int   g_count[N_NODES_];
__device__ int   g_offs[N_NODES_ + 1];
__device__ int   g_cursor[N_NODES_];
__device__ int   g_perm[N_EDGES_];
__device__ int   g_src_sorted[N_EDGES_];
__device__ float g_fc_sorted[N_EDGES_];
__device__ float g_rbf_sorted[(size_t)N_EDGES_ * NUM_BASIS_];
__device__ unsigned int g_syncA;

// ---------------- packed f32x2 helpers ----------------
__device__ __forceinline__ unsigned long long pack2(float lo, float hi) {
    unsigned long long r;
    asm("mov.b64 %0, {%1, %2};" : "=l"(r) : "f"(lo), "f"(hi));
    return r;
}
__device__ __forceinline__ float2 unpack2(unsigned long long v) {
    float2 f;
    asm("mov.b64 {%0, %1}, %2;" : "=f"(f.x), "=f"(f.y) : "l"(v));
    return f;
}
#define FFMA2(acc, r, w) \
    asm("fma.rn.f32x2 %0, %1, %2, %0;" : "+l"(acc) : "l"(r), "l"(w))

// ---------------------------------------------------------------------------
__device__ __forceinline__ void grid_barrier(unsigned int* ctr, int nblk) {
    __syncthreads();
    if (threadIdx.x == 0) {
        __threadfence();
        unsigned int arrive = atomicAdd(ctr, 1u) + 1u;
        unsigned int target = ((arrive - 1u) / (unsigned)nblk + 1u) * (unsigned)nblk;
        unsigned int v;
        do {
            asm volatile("ld.acquire.gpu.u32 %0, [%1];" : "=r"(v) : "l"(ctr));
        } while (v < target);
    }
    __syncthreads();
}

// ---------------------------------------------------------------------------
// Fused counting sort + sorted-metadata materialization.
// ---------------------------------------------------------------------------
__global__ __launch_bounds__(1024) void sort_kernel(
    const int* __restrict__ edge_index, const float* __restrict__ fcut,
    const float* __restrict__ rbf) {
    const int gsz = gridDim.x * blockDim.x;
    const int gtid = blockIdx.x * blockDim.x + threadIdx.x;

    for (int e = gtid; e < N_EDGES_; e += gsz)
        atomicAdd(&g_count[edge_index[e]], 1);
    grid_barrier(&g_syncA, SORT_BLKS_);

    if (blockIdx.x == 0) {
        __shared__ int s[1024];
        const int C = 30;
        const int t = threadIdx.x;
        const int base = t * C;
        int local[C];
        int sum = 0;
        #pragma unroll
        for (int j = 0; j < C; j++) {
            int i = base + j;
            int v = (i < N_NODES_) ? g_count[i] : 0;
            local[j] = sum;
            sum += v;
        }
        s[t] = sum;
        __syncthreads();
        #pragma unroll
        for (int d = 1; d < 1024; d <<= 1) {
            int x = (t >= d) ? s[t - d] : 0;
            __syncthreads();
            s[t] += x;
            __syncthreads();
        }
        int pre = (t > 0) ? s[t - 1] : 0;
        #pragma unroll
        for (int j = 0; j < C; j++) {
            int i = base + j;
            if (i < N_NODES_) {
                int o = pre + local[j];
                g_offs[i] = o;
                g_cursor[i] = o;
                g_count[i] = 0;
            }
        }
        if (t == 1023) g_offs[N_NODES_] = s[1023];
    }
    grid_barrier(&g_syncA, SORT_BLKS_);

    for (int e = gtid; e < N_EDGES_; e += gsz) {
        int d = edge_index[e];
        int p = atomicAdd(&g_cursor[d], 1);
        g_perm[p] = e;
        g_src_sorted[p] = edge_index[N_EDGES_ + e];
        g_fc_sorted[p] = fcut[e];
    }
    grid_barrier(&g_syncA, SORT_BLKS_);

    for (long long i = gtid; i < (long long)N_EDGES_ * NUM_BASIS_; i += gsz) {
        int p = (int)(i / NUM_BASIS_);
        int k = (int)(i - (long long)p * NUM_BASIS_);
        g_rbf_sorted[i] = rbf[(size_t)g_perm[p] * NUM_BASIS_ + k];
    }
}

// ---------------------------------------------------------------------------
// SGEMM 64x64, 4x4 contiguous microtile
// ---------------------------------------------------------------------------
template <bool DO_SILU>
__global__ __launch_bounds__(256) void sgemm_bias(
    const float* __restrict__ A, const float* __restrict__ B,
    const float* __restrict__ bias, float* __restrict__ C,
    int M, int N, int K) {
    __shared__ __align__(16) float As[16][68];
    __shared__ __align__(16) float Bs[16][64];
    const int bm = blockIdx.y * 64;
    const int bn = blockIdx.x * 64;
    const int tid = threadIdx.x;
    const int tx = tid & 15;
    const int ty = tid >> 4;

    float acc[4][4] = {};

    for (int k0 = 0; k0 < K; k0 += 16) {
        #pragma unroll
        for (int i = 0; i < 4; i++) {
            int idx = tid + 256 * i;
            int m = idx >> 4, k = idx & 15;
            int gm = bm + m;
            As[k][m] = (gm < M) ? A[(size_t)gm * K + k0 + k] : 0.0f;
        }
        #pragma unroll
        for (int i = 0; i < 4; i++) {
            int idx = tid + 256 * i;
            int k = idx >> 6, n = idx & 63;
            Bs[k][n] = B[(size_t)(k0 + k) * N + bn + n];
        }
        __syncthreads();
        #pragma unroll
        for (int k = 0; k < 16; k++) {
            float4 aq = *reinterpret_cast<const float4*>(&As[k][ty * 4]);
            float4 bq = *reinterpret_cast<const float4*>(&Bs[k][tx * 4]);
            float a[4] = {aq.x, aq.y, aq.z, aq.w};
            float b[4] = {bq.x, bq.y, bq.z, bq.w};
            #pragma unroll
            for (int i = 0; i < 4; i++)
                #pragma unroll
                for (int j = 0; j < 4; j++)
                    acc[i][j] = fmaf(a[i], b[j], acc[i][j]);
        }
        __syncthreads();
    }

    float4 bq = *reinterpret_cast<const float4*>(&bias[bn + tx * 4]);
    float bv[4] = {bq.x, bq.y, bq.z, bq.w};
    #pragma unroll
    for (int i = 0; i < 4; i++) {
        int m = bm + ty * 4 + i;
        if (m >= M) continue;
        float4 o;
        float* op = &o.x;
        #pragma unroll
        for (int j = 0; j < 4; j++) {
            float v = acc[i][j] + bv[j];
            if (DO_SILU) v = v / (1.0f + expf(-v));
            op[j] = v;
        }
        *reinterpret_cast<float4*>(&C[(size_t)m * N + bn + tx * 4]) = o;
    }
}

// ---------------------------------------------------------------------------
// Persistent node kernel. Per 16-edge chunk:
//  A: issue cp.async staging of rsh -> smem (each thread copies its own col)
//  B: meta fill (sorted arrays, sequential)
//  C: gate phase (2x8 edges, scalar_out gather one sub-batch ahead, f32x2)
//  D: msg phase (cp.async.wait; rsh from smem; x_sph one sub-batch ahead)
// ---------------------------------------------------------------------------
__device__ __forceinline__ int irrep_of(int k) {
    if (k < 128) return k;
    if (k < 320) return 128 + (k - 128) / 3;
    return 192 + (k - 320) / 5;
}

__global__ __launch_bounds__(576, 1) void node_kernel(
    const float* __restrict__ rsh,
    const float* __restrict__ Wrbf, const float* __restrict__ brbf,
    const float* __restrict__ x_scalar, const float* __restrict__ x_sph,
    float* __restrict__ out_scalar, float* __restrict__ out_sph) {
    const float* __restrict__ scalar_out = g_scalar_out;

    extern __shared__ float dyn_s[];
    float* gate32 = dyn_s;                       // [MAXD_][448]
    float* rsh_s  = dyn_s + GATE_FLOATS_;        // [MAXD_][480]

    __shared__ __align__(8) float2 rbf_p[MAXD_ / 2][NUM_BASIS_];
    __shared__ int   src_s[MAXD_];
    __shared__ float fc_s[MAXD_];

    const int t = threadIdx.x;

    unsigned long long wp[NUM_BASIS_];
    #pragma unroll
    for (int k = 0; k < NUM_BASIS_; k++) {
        float wv = Wrbf[k * HIDDEN_ + t];
        wp[k] = pack2(wv, wv);
    }
    const unsigned long long bbp = pack2(brbf[t], brbf[t]);
    const int ir = (t < SPH_DIM_) ? irrep_of(t) : 0;
    const bool is_sph = (t < SPH_DIM_);

    // keep padded rbf lanes finite (stale values are multiplied by fc=0)
    for (int i = t; i < (MAXD_ / 2) * NUM_BASIS_ * 2; i += 576)
        reinterpret_cast<float*>(rbf_p)[i] = 0.0f;

    for (int n = blockIdx.x; n < N_NODES_; n += gridDim.x) {
        const int off = g_offs[n];
        const int deg = g_offs[n + 1] - off;

        float acc_sph = 0.0f;
        float acc_sc  = 0.0f;

        for (int c0 = 0; c0 < deg; c0 += MAXD_) {
            const int cnt = min(MAXD_, deg - c0);
            const int bp = off + c0;

            __syncthreads();   // all smem from previous chunk consumed

            // ---- A: stage rsh via cp.async (no smem dependency: perm is
            //      read directly, broadcast across the warp, L1/L2-hot) ----
            if (is_sph) {
                #pragma unroll
                for (int e = 0; e < MAXD_; e++) {
                    int j = (e < cnt) ? e : cnt - 1;
                    int eid = __ldg(&g_perm[bp + j]);
                    unsigned int dst = (unsigned int)
                        __cvta_generic_to_shared(&rsh_s[e * SPH_DIM_ + t]);
                    const float* srcp = &rsh[(size_t)eid * SPH_DIM_ + t];
                    asm volatile(
                        "cp.async.ca.shared.global [%0], [%1], 4;"
                        :: "r"(dst), "l"(srcp));
                }
                asm volatile("cp.async.commit_group;" ::: "memory");
            }

            // ---- B: meta fill (sequential loads from sorted arrays) ----
            if (t < MAXD_) {
                int j = (t < cnt) ? t : cnt - 1;
                src_s[t] = __ldg(&g_src_sorted[bp + j]);
                fc_s[t]  = (t < cnt) ? __ldg(&g_fc_sorted[bp + t]) : 0.0f;
            }
            for (int i = t; i < cnt * NUM_BASIS_; i += 576) {
                int e = i / NUM_BASIS_, k = i - e * NUM_BASIS_;
                float v = __ldg(&g_rbf_sorted[(size_t)bp * NUM_BASIS_ + i]);
                reinterpret_cast<float*>(&rbf_p[e >> 1][k])[e & 1] = v;
            }
            __syncthreads();

            const int nbs = (cnt + EPB_ - 1) / EPB_;   // 1..2

            // ---- C: gate phase (no internal barriers) ----
            {
                float sC[EPB_], sN[EPB_];
                #pragma unroll
                for (int e = 0; e < EPB_; e++)
                    sC[e] = __ldg(&scalar_out[(size_t)src_s[e] * HIDDEN_ + t]);

                for (int b = 0; b < nbs; b++) {
                    const int base = b * EPB_;
                    if (b + 1 < nbs) {
                        #pragma unroll
                        for (int e = 0; e < EPB_; e++)
                            sN[e] = __ldg(&scalar_out[
                                (size_t)src_s[base + EPB_ + e] * HIDDEN_ + t]);
                    }

                    float a[EPB_];
                    #pragma unroll
                    for (int j = 0; j < EPB_ / 2; j++) {
                        unsigned long long acc = bbp;
                        const unsigned long long* rp =
                            reinterpret_cast<const unsigned long long*>(
                                &rbf_p[(base >> 1) + j][0]);
                        #pragma unroll
                        for (int k = 0; k < NUM_BASIS_; k++)
                            FFMA2(acc, rp[k], wp[k]);
                        float2 u = unpack2(acc);
                        a[2 * j]     = u.x;
                        a[2 * j + 1] = u.y;
                    }

                    #pragma unroll
                    for (int e = 0; e < EPB_; e++)
                        sC[e] = sC[e] * (a[e] * fc_s[base + e]);

                    if (t < 2 * NUM_IRREPS_) {
                        #pragma unroll
                        for (int e = 0; e < EPB_; e++)
                            gate32[(base + e) * 2 * NUM_IRREPS_ + t] = sC[e];
                    } else {
                        #pragma unroll
                        for (int e = 0; e < EPB_; e++) acc_sc += sC[e];
                    }
                    #pragma unroll
                    for (int e = 0; e < EPB_; e++) sC[e] = sN[e];
                }
            }
            __syncthreads();   // gates ready

            // ---- D: message phase (no internal barriers) ----
            if (is_sph) {
                asm volatile("cp.async.wait_group 0;" ::: "memory");
                float xC[EPB_], xN[EPB_];
                #pragma unroll
                for (int e = 0; e < EPB_; e++)
                    xC[e] = __ldg(&x_sph[(size_t)src_s[e] * SPH_DIM_ + t]);

                for (int b = 0; b < nbs; b++) {
                    const int base = b * EPB_;
                    if (b + 1 < nbs) {
                        #pragma unroll
                        for (int e = 0; e < EPB_; e++)
                            xN[e] = __ldg(&x_sph[
                                (size_t)src_s[base + EPB_ + e] * SPH_DIM_ + t]);
                    }
                    #pragma unroll
                    for (int e = 0; e < EPB_; e++) {
                        const float* ge =
                            gate32 + (base + e) * 2 * NUM_IRREPS_;
                        float rv = rsh_s[(base + e) * SPH_DIM_ + t];
                        acc_sph = fmaf(xC[e], ge[ir], acc_sph);
                        acc_sph = fmaf(rv, ge[NUM_IRREPS_ + ir], acc_sph);
                    }
                    #pragma unroll
                    for (int e = 0; e < EPB_; e++) xC[e] = xN[e];
                }
            } else {
                asm volatile("cp.async.wait_group 0;" ::: "memory");
            }
        }

        // residual + single write (covers deg==0 too)
        if (is_sph)
            out_sph[(size_t)n * SPH_DIM_ + t] =
                x_sph[(size_t)n * SPH_DIM_ + t] + acc_sph;
        if (t >= 2 * NUM_IRREPS_) {
            int c = t - 2 * NUM_IRREPS_;
            out_scalar[(size_t)n * NODE_DIM_ + c] =
                x_scalar[(size_t)n * NODE_DIM_ + c] + acc_sc;
        }
    }
}

// ---------------------------------------------------------------------------
extern "C" void kernel_launch(void* const* d_in, const int* in_sizes, int n_in,
                              void* d_out, int out_size) {
    const float* x_scalar = (const float*)d_in[0];
    const float* x_sph    = (const float*)d_in[1];
    const float* rbf      = (const float*)d_in[2];
    const float* fcut     = (const float*)d_in[3];
    const float* rsh      = (const float*)d_in[4];
    const int*   eidx     = (const int*)d_in[5];
    const float* W1       = (const float*)d_in[6];
    const float* b1       = (const float*)d_in[7];
    const float* W2       = (const float*)d_in[8];
    const float* b2       = (const float*)d_in[9];
    const float* Wrbf     = (const float*)d_in[10];
    const float* brbf     = (const float*)d_in[11];

    float* out        = (float*)d_out;
    float* out_scalar = out;
    float* out_sph    = out + (size_t)N_NODES_ * NODE_DIM_;

    float* hidden = nullptr;
    float* so     = nullptr;
    cudaGetSymbolAddress((void**)&hidden, g_hidden);
    cudaGetSymbolAddress((void**)&so, g_scalar_out);

    static int smem_set = 0;
    if (!smem_set) {
        cudaFuncSetAttribute(node_kernel,
                             cudaFuncAttributeMaxDynamicSharedMemorySize,
                             DYN_BYTES_);
        smem_set = 1;
    }

    sort_kernel<<<SORT_BLKS_, 1024>>>(eidx, fcut, rbf);                      // 0
    {
        dim3 grid(NODE_DIM_ / 64, (N_NODES_ + 63) / 64);
        sgemm_bias<true><<<grid, 256>>>(x_scalar, W1, b1, hidden,
                                        N_NODES_, NODE_DIM_, NODE_DIM_);     // 1
    }
    {
        dim3 grid(HIDDEN_ / 64, (N_NODES_ + 63) / 64);
        sgemm_bias<false><<<grid, 256>>>(hidden, W2, b2, so,
                                         N_NODES_, HIDDEN_, NODE_DIM_);      // 2
    }
    node_kernel<<<148, 576, DYN_BYTES_>>>(rsh, Wrbf, brbf,
                                          x_scalar, x_sph,
                                          out_scalar, out_sph);              // 3
}

// round 13
// speedup vs baseline: 1.2523x; 1.2523x over previous
#include <cuda_runtime.h>
#include <cstdint>
#include <math.h>

#define NODE_DIM_   128
#define NUM_IRREPS_ 224
#define SPH_DIM_    480
#define HIDDEN_     576
#define NUM_BASIS_  20
#define N_NODES_    30000
#define N_EDGES_    480000
#define EPB_        8
#define MAXD_       32
#define SORT_BLKS_  148

// Scratch (device globals)
__device__ float g_hidden[(size_t)N_NODES_ * NODE_DIM_];
__device__ float g_scalar_out[(size_t)N_NODES_ * HIDDEN_];
__device__ int   g_count[N_NODES_];
__device__ int   g_offs[N_NODES_ + 1];
__device__ int   g_cursor[N_NODES_];
__device__ int   g_perm[N_EDGES_];
__device__ int   g_src_sorted[N_EDGES_];
__device__ float g_fc_sorted[N_EDGES_];
__device__ float g_rbf_sorted[(size_t)N_EDGES_ * NUM_BASIS_];
__device__ unsigned int g_syncA;

// ---------------------------------------------------------------------------
__device__ __forceinline__ void grid_barrier(unsigned int* ctr, int nblk) {
    __syncthreads();
    if (threadIdx.x == 0) {
        __threadfence();
        unsigned int arrive = atomicAdd(ctr, 1u) + 1u;
        unsigned int target = ((arrive - 1u) / (unsigned)nblk + 1u) * (unsigned)nblk;
        unsigned int v;
        do {
            asm volatile("ld.acquire.gpu.u32 %0, [%1];" : "=r"(v) : "l"(ctr));
        } while (v < target);
    }
    __syncthreads();
}

// ---------------------------------------------------------------------------
// Fused counting sort + sorted-metadata materialization.
// ---------------------------------------------------------------------------
__global__ __launch_bounds__(1024) void sort_kernel(
    const int* __restrict__ edge_index, const float* __restrict__ fcut,
    const float* __restrict__ rbf) {
    const int gsz = gridDim.x * blockDim.x;
    const int gtid = blockIdx.x * blockDim.x + threadIdx.x;

    for (int e = gtid; e < N_EDGES_; e += gsz)
        atomicAdd(&g_count[edge_index[e]], 1);
    grid_barrier(&g_syncA, SORT_BLKS_);

    if (blockIdx.x == 0) {
        __shared__ int s[1024];
        const int C = 30;
        const int t = threadIdx.x;
        const int base = t * C;
        int local[C];
        int sum = 0;
        #pragma unroll
        for (int j = 0; j < C; j++) {
            int i = base + j;
            int v = (i < N_NODES_) ? g_count[i] : 0;
            local[j] = sum;
            sum += v;
        }
        s[t] = sum;
        __syncthreads();
        #pragma unroll
        for (int d = 1; d < 1024; d <<= 1) {
            int x = (t >= d) ? s[t - d] : 0;
            __syncthreads();
            s[t] += x;
            __syncthreads();
        }
        int pre = (t > 0) ? s[t - 1] : 0;
        #pragma unroll
        for (int j = 0; j < C; j++) {
            int i = base + j;
            if (i < N_NODES_) {
                int o = pre + local[j];
                g_offs[i] = o;
                g_cursor[i] = o;
                g_count[i] = 0;
            }
        }
        if (t == 1023) g_offs[N_NODES_] = s[1023];
    }
    grid_barrier(&g_syncA, SORT_BLKS_);

    for (int e = gtid; e < N_EDGES_; e += gsz) {
        int d = edge_index[e];
        int p = atomicAdd(&g_cursor[d], 1);
        g_perm[p] = e;
        g_src_sorted[p] = edge_index[N_EDGES_ + e];
        g_fc_sorted[p] = fcut[e];
    }
    grid_barrier(&g_syncA, SORT_BLKS_);

    for (long long i = gtid; i < (long long)N_EDGES_ * NUM_BASIS_; i += gsz) {
        int p = (int)(i / NUM_BASIS_);
        int k = (int)(i - (long long)p * NUM_BASIS_);
        g_rbf_sorted[i] = rbf[(size_t)g_perm[p] * NUM_BASIS_ + k];
    }
}

// ---------------------------------------------------------------------------
// SGEMM 64x64, 4x4 contiguous microtile
// ---------------------------------------------------------------------------
template <bool DO_SILU>
__global__ __launch_bounds__(256) void sgemm_bias(
    const float* __restrict__ A, const float* __restrict__ B,
    const float* __restrict__ bias, float* __restrict__ C,
    int M, int N, int K) {
    __shared__ __align__(16) float As[16][68];
    __shared__ __align__(16) float Bs[16][64];
    const int bm = blockIdx.y * 64;
    const int bn = blockIdx.x * 64;
    const int tid = threadIdx.x;
    const int tx = tid & 15;
    const int ty = tid >> 4;

    float acc[4][4] = {};

    for (int k0 = 0; k0 < K; k0 += 16) {
        #pragma unroll
        for (int i = 0; i < 4; i++) {
            int idx = tid + 256 * i;
            int m = idx >> 4, k = idx & 15;
            int gm = bm + m;
            As[k][m] = (gm < M) ? A[(size_t)gm * K + k0 + k] : 0.0f;
        }
        #pragma unroll
        for (int i = 0; i < 4; i++) {
            int idx = tid + 256 * i;
            int k = idx >> 6, n = idx & 63;
            Bs[k][n] = B[(size_t)(k0 + k) * N + bn + n];
        }
        __syncthreads();
        #pragma unroll
        for (int k = 0; k < 16; k++) {
            float4 aq = *reinterpret_cast<const float4*>(&As[k][ty * 4]);
            float4 bq = *reinterpret_cast<const float4*>(&Bs[k][tx * 4]);
            float a[4] = {aq.x, aq.y, aq.z, aq.w};
            float b[4] = {bq.x, bq.y, bq.z, bq.w};
            #pragma unroll
            for (int i = 0; i < 4; i++)
                #pragma unroll
                for (int j = 0; j < 4; j++)
                    acc[i][j] = fmaf(a[i], b[j], acc[i][j]);
        }
        __syncthreads();
    }

    float4 bq = *reinterpret_cast<const float4*>(&bias[bn + tx * 4]);
    float bv[4] = {bq.x, bq.y, bq.z, bq.w};
    #pragma unroll
    for (int i = 0; i < 4; i++) {
        int m = bm + ty * 4 + i;
        if (m >= M) continue;
        float4 o;
        float* op = &o.x;
        #pragma unroll
        for (int j = 0; j < 4; j++) {
            float v = acc[i][j] + bv[j];
            if (DO_SILU) v = v / (1.0f + expf(-v));
            op[j] = v;
        }
        *reinterpret_cast<float4*>(&C[(size_t)m * N + bn + tx * 4]) = o;
    }
}

// ---------------------------------------------------------------------------
// Persistent node kernel, cross-barrier pipelined:
// per iteration: store gates(b) [regs gathered last iter] -> issue gathers(b+1)
//                -> barrier -> messages(b) [x/r gathered last iter].
// Non-spherical warps (t>=480) prefetch next chunk's rsh rows to L2.
// ---------------------------------------------------------------------------
__device__ __forceinline__ int irrep_of(int k) {
    if (k < 128) return k;
    if (k < 320) return 128 + (k - 128) / 3;
    return 192 + (k - 320) / 5;
}

__global__ __launch_bounds__(576, 1) void node_kernel(
    const float* __restrict__ rsh,
    const float* __restrict__ Wrbf, const float* __restrict__ brbf,
    const float* __restrict__ x_scalar, const float* __restrict__ x_sph,
    float* __restrict__ out_scalar, float* __restrict__ out_sph) {
    const float* __restrict__ scalar_out = g_scalar_out;

    __shared__ __align__(16) float rbf_s[MAXD_][24];
    __shared__ int   eid_s[MAXD_];
    __shared__ int   src_s[MAXD_];
    __shared__ float fc_s[MAXD_];
    __shared__ float gate_s[2][EPB_][2 * NUM_IRREPS_];

    const int t = threadIdx.x;

    float w[NUM_BASIS_];
    #pragma unroll
    for (int k = 0; k < NUM_BASIS_; k++) w[k] = Wrbf[k * HIDDEN_ + t];
    const float bb = brbf[t];
    const int ir = (t < SPH_DIM_) ? irrep_of(t) : 0;
    const bool is_sph = (t < SPH_DIM_);

    for (int n = blockIdx.x; n < N_NODES_; n += gridDim.x) {
        const int off = g_offs[n];
        const int deg = g_offs[n + 1] - off;

        float acc_sph = 0.0f;
        float acc_sc  = 0.0f;

        for (int c0 = 0; c0 < deg; c0 += MAXD_) {
            const int cnt = min(MAXD_, deg - c0);
            const int bp = off + c0;
            const int nb = (cnt + EPB_ - 1) / EPB_;   // 1..4

            __syncthreads();   // prev chunk's smem fully consumed

            // ---- batch-0 gathers issued BEFORE meta barrier (direct loads)
            float sA[EPB_], xA[EPB_], rA[EPB_];
            #pragma unroll
            for (int e = 0; e < EPB_; e++) {
                int j = (e < cnt) ? e : cnt - 1;
                int sp = __ldg(&g_src_sorted[bp + j]);
                sA[e] = __ldg(&scalar_out[(size_t)sp * HIDDEN_ + t]);
                if (is_sph) {
                    int ep = __ldg(&g_perm[bp + j]);
                    xA[e] = __ldg(&x_sph[(size_t)sp * SPH_DIM_ + t]);
                    rA[e] = __ldcs(&rsh[(size_t)ep * SPH_DIM_ + t]);
                }
            }

            // ---- meta fill (sorted arrays, sequential) ----
            if (t < MAXD_) {
                int j = (t < cnt) ? t : cnt - 1;
                eid_s[t] = __ldg(&g_perm[bp + j]);
                src_s[t] = __ldg(&g_src_sorted[bp + j]);
                fc_s[t]  = (t < cnt) ? __ldg(&g_fc_sorted[bp + t]) : 0.0f;
            }
            for (int i = t; i < cnt * NUM_BASIS_; i += 576) {
                int e = i / NUM_BASIS_, k = i - e * NUM_BASIS_;
                rbf_s[e][k] = __ldg(&g_rbf_sorted[(size_t)bp * NUM_BASIS_ + i]);
            }

            // ---- non-sph warps: prefetch next chunk's rsh rows to L2 ----
            if (!is_sph) {
                int rem = deg - c0 - MAXD_;
                if (rem > 0) {
                    int nxt = min(rem, MAXD_);
                    int u = t - SPH_DIM_;              // 0..95
                    for (int i = u; i < nxt * 15; i += 96) {
                        int e = i / 15, line = i - e * 15;
                        int en = __ldg(&g_perm[bp + MAXD_ + e]);
                        const float* pf = &rsh[(size_t)en * SPH_DIM_ + line * 32];
                        asm volatile("prefetch.global.L2 [%0];" :: "l"(pf));
                    }
                }
            }
            __syncthreads();

            // ---- pipelined batch loop ----
            float sB[EPB_], xB[EPB_], rB[EPB_];
            for (int b = 0; b < nb; b++) {
                const int base = b * EPB_;

                // issue next batch's gathers first (overlap the FMA chain)
                if (b + 1 < nb) {
                    #pragma unroll
                    for (int e = 0; e < EPB_; e++) {
                        int sp = src_s[base + EPB_ + e];
                        sB[e] = __ldg(&scalar_out[(size_t)sp * HIDDEN_ + t]);
                        if (is_sph) {
                            int ep = eid_s[base + EPB_ + e];
                            xB[e] = __ldg(&x_sph[(size_t)sp * SPH_DIM_ + t]);
                            rB[e] = __ldcs(&rsh[(size_t)ep * SPH_DIM_ + t]);
                        }
                    }
                }

                // gates for batch b (sA gathered >= 1 phase ago)
                float a[EPB_];
                #pragma unroll
                for (int e = 0; e < EPB_; e++) {
                    const float4* rp =
                        reinterpret_cast<const float4*>(&rbf_s[base + e][0]);
                    float4 q0 = rp[0], q1 = rp[1], q2 = rp[2], q3 = rp[3], q4 = rp[4];
                    float v = bb;
                    v = fmaf(q0.x, w[0],  v); v = fmaf(q0.y, w[1],  v);
                    v = fmaf(q0.z, w[2],  v); v = fmaf(q0.w, w[3],  v);
                    v = fmaf(q1.x, w[4],  v); v = fmaf(q1.y, w[5],  v);
                    v = fmaf(q1.z, w[6],  v); v = fmaf(q1.w, w[7],  v);
                    v = fmaf(q2.x, w[8],  v); v = fmaf(q2.y, w[9],  v);
                    v = fmaf(q2.z, w[10], v); v = fmaf(q2.w, w[11], v);
                    v = fmaf(q3.x, w[12], v); v = fmaf(q3.y, w[13], v);
                    v = fmaf(q3.z, w[14], v); v = fmaf(q3.w, w[15], v);
                    v = fmaf(q4.x, w[16], v); v = fmaf(q4.y, w[17], v);
                    v = fmaf(q4.z, w[18], v); v = fmaf(q4.w, w[19], v);
                    a[e] = v;
                }
                #pragma unroll
                for (int e = 0; e < EPB_; e++)
                    sA[e] = sA[e] * (a[e] * fc_s[base + e]);

                if (t < 2 * NUM_IRREPS_) {
                    #pragma unroll
                    for (int e = 0; e < EPB_; e++) gate_s[b & 1][e][t] = sA[e];
                } else {
                    #pragma unroll
                    for (int e = 0; e < EPB_; e++) acc_sc += sA[e];
                }
                __syncthreads();

                // messages batch b (xA/rA gathered >= 1 phase ago)
                if (is_sph) {
                    #pragma unroll
                    for (int e = 0; e < EPB_; e++) {
                        const float* ge = gate_s[b & 1][e];
                        acc_sph = fmaf(xA[e], ge[ir], acc_sph);
                        acc_sph = fmaf(rA[e], ge[NUM_IRREPS_ + ir], acc_sph);
                    }
                }

                // rotate pipeline registers
                #pragma unroll
                for (int e = 0; e < EPB_; e++) {
                    sA[e] = sB[e];
                    if (is_sph) { xA[e] = xB[e]; rA[e] = rB[e]; }
                }
            }
        }

        // residual + single write (covers deg==0 too)
        if (is_sph)
            out_sph[(size_t)n * SPH_DIM_ + t] =
                x_sph[(size_t)n * SPH_DIM_ + t] + acc_sph;
        if (t >= 2 * NUM_IRREPS_) {
            int c = t - 2 * NUM_IRREPS_;
            out_scalar[(size_t)n * NODE_DIM_ + c] =
                x_scalar[(size_t)n * NODE_DIM_ + c] + acc_sc;
        }
    }
}

// ---------------------------------------------------------------------------
extern "C" void kernel_launch(void* const* d_in, const int* in_sizes, int n_in,
                              void* d_out, int out_size) {
    const float* x_scalar = (const float*)d_in[0];
    const float* x_sph    = (const float*)d_in[1];
    const float* rbf      = (const float*)d_in[2];
    const float* fcut     = (const float*)d_in[3];
    const float* rsh      = (const float*)d_in[4];
    const int*   eidx     = (const int*)d_in[5];
    const float* W1       = (const float*)d_in[6];
    const float* b1       = (const float*)d_in[7];
    const float* W2       = (const float*)d_in[8];
    const float* b2       = (const float*)d_in[9];
    const float* Wrbf     = (const float*)d_in[10];
    const float* brbf     = (const float*)d_in[11];

    float* out        = (float*)d_out;
    float* out_scalar = out;
    float* out_sph    = out + (size_t)N_NODES_ * NODE_DIM_;

    float* hidden = nullptr;
    float* so     = nullptr;
    cudaGetSymbolAddress((void**)&hidden, g_hidden);
    cudaGetSymbolAddress((void**)&so, g_scalar_out);

    sort_kernel<<<SORT_BLKS_, 1024>>>(eidx, fcut, rbf);                      // 0
    {
        dim3 grid(NODE_DIM_ / 64, (N_NODES_ + 63) / 64);
        sgemm_bias<true><<<grid, 256>>>(x_scalar, W1, b1, hidden,
                                        N_NODES_, NODE_DIM_, NODE_DIM_);     // 1
    }
    {
        dim3 grid(HIDDEN_ / 64, (N_NODES_ + 63) / 64);
        sgemm_bias<false><<<grid, 256>>>(hidden, W2, b2, so,
                                         N_NODES_, HIDDEN_, NODE_DIM_);      // 2
    }
    node_kernel<<<148, 576>>>(rsh, Wrbf, brbf,
                              x_scalar, x_sph, out_scalar, out_sph);         // 3
}